// round 15
// baseline (speedup 1.0000x reference)
#include <cuda_runtime.h>

#define NROWS   341
#define CSTRIDE 16         // floats per row (differenced coeffs, col15 = 1-C14)
#define TPB     128
#define SPT     2
#define NSAMP   262144

typedef unsigned long long u64;

// DIFFERENCED coefficient rows: dC[r][0]=C0, dC[r][m]=Cm-Cm-1, dC[r][15]=1-C14.
// Row layout: dim0 at 0, dim1 [1,5), dim2 [5,21), dim3 [21,85), dim4 [85,341).
__device__ float gC[NROWS * CSTRIDE];

// ---------------- packed f32x2 helpers ----------------
__device__ __forceinline__ u64 pk2(float a, float b) {
    u64 r; asm("mov.b64 %0,{%1,%2};" : "=l"(r) : "f"(a), "f"(b)); return r;
}
__device__ __forceinline__ void upk2(u64 d, float& a, float& b) {
    asm("mov.b64 {%0,%1},%2;" : "=f"(a), "=f"(b) : "l"(d));
}
__device__ __forceinline__ u64 fma2_(u64 a, u64 b, u64 c) {
    u64 d; asm("fma.rn.f32x2 %0,%1,%2,%3;" : "=l"(d) : "l"(a), "l"(b), "l"(c)); return d;
}
__device__ __forceinline__ u64 mul2_(u64 a, u64 b) {
    u64 d; asm("mul.rn.f32x2 %0,%1,%2;" : "=l"(d) : "l"(a), "l"(b)); return d;
}

// ---------------------------------------------------------------------------
// Prep: constrained(A), then forward-difference along the coefficient axis.
// ---------------------------------------------------------------------------
__global__ void bf_prep(const float* __restrict__ A0, const float* __restrict__ A1,
                        const float* __restrict__ A2, const float* __restrict__ A3,
                        const float* __restrict__ A4) {
    int r = threadIdx.x;
    if (r >= NROWS) return;
    const float* A; int lr;
    if (r == 0)      { A = A0; lr = 0;      }
    else if (r < 5)  { A = A1; lr = r - 1;  }
    else if (r < 21) { A = A2; lr = r - 5;  }
    else if (r < 85) { A = A3; lr = r - 21; }
    else             { A = A4; lr = r - 85; }
    float s = 0.f, prev = 0.f;
    for (int m = 0; m < 15; m++) {
        float a  = A[lr * 15 + m];
        float sp = (a > 20.f) ? a : log1pf(expf(a));
        s += sp;
        float sig = 1.f / (1.f + expf(-s));
        float c = 2.f * (sig - 0.5f);
        gC[r * CSTRIDE + m] = c - prev;
        prev = c;
    }
    gC[r * CSTRIDE + 15] = 1.f - prev;
}

// ---------------------------------------------------------------------------
// One row, two samples. Each LDS.128 yields two (dc_m, dc_m+1) pairs consumed
// by fma.rn.f32x2. Row weight arrives PACKED (wa, wb); duplicated with 2 movs.
// Cost: 4x LDS.128 + 2 movs + 16x FFMA2 per row for BOTH samples.
// ---------------------------------------------------------------------------
__device__ __forceinline__ void row_pw(const u64* __restrict__ sC, int row,
                                       u64 wAB, u64 aA[8], u64 aB[8]) {
    const ulonglong2* p = reinterpret_cast<const ulonglong2*>(sC + row * (CSTRIDE / 2));
    float wa, wb; upk2(wAB, wa, wb);
    u64 wA = pk2(wa, wa);
    u64 wB = pk2(wb, wb);
#pragma unroll
    for (int q = 0; q < 4; q++) {
        ulonglong2 c = p[q];
        aA[2*q]     = fma2_(wA, c.x, aA[2*q]);
        aA[2*q + 1] = fma2_(wA, c.y, aA[2*q + 1]);
        aB[2*q]     = fma2_(wB, c.x, aB[2*q]);
        aB[2*q + 1] = fma2_(wB, c.y, aB[2*q + 1]);
    }
}

// ---------------------------------------------------------------------------
// Derivative eval from DIFFERENCED coefficients:
// f = sum_m dcoef[m] * comb16[m] * u^m v^(15-m).
// ---------------------------------------------------------------------------
__device__ __forceinline__ float deriv16d(const float dc[16], float xi) {
    const float comb16[15] = {16.f, 240.f, 1680.f, 7280.f, 21840.f, 48048.f,
                              80080.f, 102960.f, 102960.f, 80080.f, 48048.f,
                              21840.f, 7280.f, 1680.f, 240.f};
    float u = xi, v = 1.f - xi;
    float F  = dc[15] * 16.f;
    float vp = 1.f;
#pragma unroll
    for (int m = 14; m >= 0; m--) {
        vp *= v;
        F = fmaf(u, F, dc[m] * comb16[m] * vp);
    }
    return F;
}
__device__ __forceinline__ float deriv16p(const u64 a[8], float xi) {
    float dc[16];
#pragma unroll
    for (int p = 0; p < 8; p++) upk2(a[p], dc[2*p], dc[2*p + 1]);
    return deriv16d(dc, xi);
}

// ---------------------------------------------------------------------------
// Main kernel: 2 samples/thread. Bases kept in SMEM ([j][tid] layout,
// conflict-free LDS.64) -> arch reg state ~66, cap 128 -> 16 warps/SM,
// with manual "spilling" to smem instead of ptxas local-memory spills.
// ---------------------------------------------------------------------------
__global__ void __launch_bounds__(TPB, 4)
bf_main(const float* __restrict__ x, float* __restrict__ out) {
    __shared__ __align__(16) float sCf[NROWS * CSTRIDE];   // 21824 B
    __shared__ __align__(16) u64   sB[16 * TPB];           // 16384 B

    const int tid  = threadIdx.x;
    const int base = blockIdx.x * (TPB * SPT);

    {   // stage differenced table (21.8 KB)
        const uint4* src = reinterpret_cast<const uint4*>(gC);
        uint4*       dst = reinterpret_cast<uint4*>(sCf);
        const int n16 = NROWS * CSTRIDE / 4;   // 1364
        for (int i = tid; i < n16; i += TPB) dst[i] = src[i];
    }

    const int s0 = base + tid;
    const int s1 = s0 + TPB;

    // build packed (sampleA, sampleB) degree-3 bases for coords 0..3 into smem
    {
        const u64 one2 = pk2(1.f, 1.f);
        const u64 neg1 = pk2(-1.f, -1.f);
        const u64 thr2 = pk2(3.f, 3.f);
#pragma unroll
        for (int j = 0; j < 4; j++) {
            u64 u = pk2(__ldg(&x[s0 * 5 + j]), __ldg(&x[s1 * 5 + j]));
            u64 v = fma2_(u, neg1, one2);
            u64 uu = mul2_(u, u), vv = mul2_(v, v);
            sB[(j * 4 + 0) * TPB + tid] = mul2_(vv, v);
            sB[(j * 4 + 1) * TPB + tid] = mul2_(mul2_(u, vv), thr2);
            sB[(j * 4 + 2) * TPB + tid] = mul2_(mul2_(uu, v), thr2);
            sB[(j * 4 + 3) * TPB + tid] = mul2_(uu, u);
        }
    }
    __syncthreads();
    const u64* sC  = reinterpret_cast<const u64*>(sCf);
    const u64* myB = sB + tid;      // myB[(j*4+k)*TPB] = packed b_j[k]

    float dA, dB;

    // ---- dim 0: single differenced row, weight 1
    {
        float dc[16];
#pragma unroll
        for (int m = 0; m < 16; m++) dc[m] = sCf[m];
        dA = deriv16d(dc, __ldg(&x[s0 * 5 + 0]));
        dB = deriv16d(dc, __ldg(&x[s1 * 5 + 0]));
    }

    // ---- dim 1 (rowbase 1)
    {
        u64 aA[8], aB[8];
#pragma unroll
        for (int m = 0; m < 8; m++) { aA[m] = 0ULL; aB[m] = 0ULL; }
#pragma unroll
        for (int k0 = 0; k0 < 4; k0++)
            row_pw(sC, 1 + k0, myB[k0 * TPB], aA, aB);
        dA *= deriv16p(aA, __ldg(&x[s0 * 5 + 1]));
        dB *= deriv16p(aB, __ldg(&x[s1 * 5 + 1]));
    }

    // ---- dim 2 (rowbase 5)
    {
        u64 aA[8], aB[8];
#pragma unroll
        for (int m = 0; m < 8; m++) { aA[m] = 0ULL; aB[m] = 0ULL; }
#pragma unroll
        for (int k0 = 0; k0 < 4; k0++) {
            u64 w0 = myB[k0 * TPB];
#pragma unroll
            for (int k1 = 0; k1 < 4; k1++)
                row_pw(sC, 5 + k0 * 4 + k1, mul2_(w0, myB[(4 + k1) * TPB]), aA, aB);
        }
        dA *= deriv16p(aA, __ldg(&x[s0 * 5 + 2]));
        dB *= deriv16p(aB, __ldg(&x[s1 * 5 + 2]));
    }

    // ---- dim 3 (rowbase 21): cache b2 in regs for the inner loop
    {
        u64 aA[8], aB[8];
#pragma unroll
        for (int m = 0; m < 8; m++) { aA[m] = 0ULL; aB[m] = 0ULL; }
        u64 b2c[4];
#pragma unroll
        for (int k = 0; k < 4; k++) b2c[k] = myB[(8 + k) * TPB];
#pragma unroll
        for (int k0 = 0; k0 < 4; k0++) {
            u64 w0 = myB[k0 * TPB];
#pragma unroll
            for (int k1 = 0; k1 < 4; k1++) {
                u64 w1 = mul2_(w0, myB[(4 + k1) * TPB]);
#pragma unroll
                for (int k2 = 0; k2 < 4; k2++)
                    row_pw(sC, 21 + (k0 * 4 + k1) * 4 + k2,
                           mul2_(w1, b2c[k2]), aA, aB);
            }
        }
        dA *= deriv16p(aA, __ldg(&x[s0 * 5 + 3]));
        dB *= deriv16p(aB, __ldg(&x[s1 * 5 + 3]));
    }

    // ---- dim 4 (rowbase 85): cache b2 & b3 in regs for the inner loops
    {
        u64 aA[8], aB[8];
#pragma unroll
        for (int m = 0; m < 8; m++) { aA[m] = 0ULL; aB[m] = 0ULL; }
        u64 b2c[4], b3c[4];
#pragma unroll
        for (int k = 0; k < 4; k++) { b2c[k] = myB[(8 + k) * TPB]; b3c[k] = myB[(12 + k) * TPB]; }
#pragma unroll
        for (int k0 = 0; k0 < 4; k0++) {
            u64 w0 = myB[k0 * TPB];
#pragma unroll
            for (int k1 = 0; k1 < 4; k1++) {
                u64 w1 = mul2_(w0, myB[(4 + k1) * TPB]);
#pragma unroll
                for (int k2 = 0; k2 < 4; k2++) {
                    u64 w2 = mul2_(w1, b2c[k2]);
#pragma unroll
                    for (int k3 = 0; k3 < 4; k3++)
                        row_pw(sC, 85 + ((k0 * 4 + k1) * 4 + k2) * 4 + k3,
                               mul2_(w2, b3c[k3]), aA, aB);
                }
            }
        }
        dA *= deriv16p(aA, __ldg(&x[s0 * 5 + 4]));
        dB *= deriv16p(aB, __ldg(&x[s1 * 5 + 4]));
    }

    out[s0] = dA;
    out[s1] = dB;
}

// ---------------------------------------------------------------------------
extern "C" void kernel_launch(void* const* d_in, const int* in_sizes, int n_in,
                              void* d_out, int out_size) {
    const float* x  = (const float*)d_in[0];
    const float* A0 = (const float*)d_in[1];
    const float* A1 = (const float*)d_in[2];
    const float* A2 = (const float*)d_in[3];
    const float* A3 = (const float*)d_in[4];
    const float* A4 = (const float*)d_in[5];
    float* out = (float*)d_out;

    bf_prep<<<1, 352>>>(A0, A1, A2, A3, A4);
    bf_main<<<NSAMP / (TPB * SPT), TPB>>>(x, out);   // 1024 blocks
}

// round 16
// speedup vs baseline: 1.3572x; 1.3572x over previous
#include <cuda_runtime.h>

#define NROWS   341
#define CSTRIDE 16         // floats per row (differenced coeffs, col15 = 1-C14)
#define TPB     128
#define SPT     2
#define NSAMP   262144

typedef unsigned long long u64;

// DIFFERENCED coefficient rows: dC[r][0]=C0, dC[r][m]=Cm-Cm-1, dC[r][15]=1-C14.
// Row layout: dim0 at 0, dim1 [1,5), dim2 [5,21), dim3 [21,85), dim4 [85,341).
__device__ float gC[NROWS * CSTRIDE];

// ---------------- packed f32x2 helpers ----------------
__device__ __forceinline__ u64 pk2(float a, float b) {
    u64 r; asm("mov.b64 %0,{%1,%2};" : "=l"(r) : "f"(a), "f"(b)); return r;
}
__device__ __forceinline__ void upk2(u64 d, float& a, float& b) {
    asm("mov.b64 {%0,%1},%2;" : "=f"(a), "=f"(b) : "l"(d));
}
__device__ __forceinline__ u64 fma2_(u64 a, u64 b, u64 c) {
    u64 d; asm("fma.rn.f32x2 %0,%1,%2,%3;" : "=l"(d) : "l"(a), "l"(b), "l"(c)); return d;
}
__device__ __forceinline__ u64 mul2_(u64 a, u64 b) {
    u64 d; asm("mul.rn.f32x2 %0,%1,%2;" : "=l"(d) : "l"(a), "l"(b)); return d;
}

// ---------------------------------------------------------------------------
// Prep: constrained(A), then forward-difference along the coefficient axis.
// ---------------------------------------------------------------------------
__global__ void bf_prep(const float* __restrict__ A0, const float* __restrict__ A1,
                        const float* __restrict__ A2, const float* __restrict__ A3,
                        const float* __restrict__ A4) {
    int r = threadIdx.x;
    if (r >= NROWS) return;
    const float* A; int lr;
    if (r == 0)      { A = A0; lr = 0;      }
    else if (r < 5)  { A = A1; lr = r - 1;  }
    else if (r < 21) { A = A2; lr = r - 5;  }
    else if (r < 85) { A = A3; lr = r - 21; }
    else             { A = A4; lr = r - 85; }
    float s = 0.f, prev = 0.f;
    for (int m = 0; m < 15; m++) {
        float a  = A[lr * 15 + m];
        float sp = (a > 20.f) ? a : log1pf(expf(a));
        s += sp;
        float sig = 1.f / (1.f + expf(-s));
        float c = 2.f * (sig - 0.5f);
        gC[r * CSTRIDE + m] = c - prev;
        prev = c;
    }
    gC[r * CSTRIDE + 15] = 1.f - prev;
}

// ---------------------------------------------------------------------------
// One row, two samples. Each LDS.128 yields two (dc_m, dc_m+1) pairs consumed
// by fma.rn.f32x2. Row weight arrives PACKED (wa, wb); duplicated with 2 movs.
// Cost: 4x LDS.128 + 2 movs + 16x FFMA2 per row for BOTH samples.
// ---------------------------------------------------------------------------
__device__ __forceinline__ void row_pw(const u64* __restrict__ sC, int row,
                                       u64 wAB, u64 aA[8], u64 aB[8]) {
    const ulonglong2* p = reinterpret_cast<const ulonglong2*>(sC + row * (CSTRIDE / 2));
    float wa, wb; upk2(wAB, wa, wb);
    u64 wA = pk2(wa, wa);
    u64 wB = pk2(wb, wb);
#pragma unroll
    for (int q = 0; q < 4; q++) {
        ulonglong2 c = p[q];
        aA[2*q]     = fma2_(wA, c.x, aA[2*q]);
        aA[2*q + 1] = fma2_(wA, c.y, aA[2*q + 1]);
        aB[2*q]     = fma2_(wB, c.x, aB[2*q]);
        aB[2*q + 1] = fma2_(wB, c.y, aB[2*q + 1]);
    }
}

// ---------------------------------------------------------------------------
// Derivative eval from DIFFERENCED coefficients:
// f = sum_m dcoef[m] * comb16[m] * u^m v^(15-m).
// ---------------------------------------------------------------------------
__device__ __forceinline__ float deriv16d(const float dc[16], float xi) {
    const float comb16[15] = {16.f, 240.f, 1680.f, 7280.f, 21840.f, 48048.f,
                              80080.f, 102960.f, 102960.f, 80080.f, 48048.f,
                              21840.f, 7280.f, 1680.f, 240.f};
    float u = xi, v = 1.f - xi;
    float F  = dc[15] * 16.f;
    float vp = 1.f;
#pragma unroll
    for (int m = 14; m >= 0; m--) {
        vp *= v;
        F = fmaf(u, F, dc[m] * comb16[m] * vp);
    }
    return F;
}
__device__ __forceinline__ float deriv16p(const u64 a[8], float xi) {
    float dc[16];
#pragma unroll
    for (int p = 0; p < 8; p++) upk2(a[p], dc[2*p], dc[2*p + 1]);
    return deriv16d(dc, xi);
}

// ---------------------------------------------------------------------------
// Main kernel: 2 samples/thread; smem bases; BOUNDED UNROLL WINDOW.
// Outer k-loops of dim3/dim4 are '#pragma unroll 1' so ptxas cannot pipeline
// LDS across hundreds of rows (the proven spill driver at cap 128).
// Inner 16-row bodies stay unrolled for ILP. 4 CTAs/SM -> 16 warps.
// ---------------------------------------------------------------------------
__global__ void __launch_bounds__(TPB, 4)
bf_main(const float* __restrict__ x, float* __restrict__ out) {
    __shared__ __align__(16) float sCf[NROWS * CSTRIDE];   // 21824 B
    __shared__ __align__(16) u64   sB[16 * TPB];           // 16384 B

    const int tid  = threadIdx.x;
    const int base = blockIdx.x * (TPB * SPT);

    {   // stage differenced table (21.8 KB)
        const uint4* src = reinterpret_cast<const uint4*>(gC);
        uint4*       dst = reinterpret_cast<uint4*>(sCf);
        const int n16 = NROWS * CSTRIDE / 4;   // 1364
        for (int i = tid; i < n16; i += TPB) dst[i] = src[i];
    }

    const int s0 = base + tid;
    const int s1 = s0 + TPB;

    // build packed (sampleA, sampleB) degree-3 bases for coords 0..3 into smem
    {
        const u64 one2 = pk2(1.f, 1.f);
        const u64 neg1 = pk2(-1.f, -1.f);
        const u64 thr2 = pk2(3.f, 3.f);
#pragma unroll
        for (int j = 0; j < 4; j++) {
            u64 u = pk2(__ldg(&x[s0 * 5 + j]), __ldg(&x[s1 * 5 + j]));
            u64 v = fma2_(u, neg1, one2);
            u64 uu = mul2_(u, u), vv = mul2_(v, v);
            sB[(j * 4 + 0) * TPB + tid] = mul2_(vv, v);
            sB[(j * 4 + 1) * TPB + tid] = mul2_(mul2_(u, vv), thr2);
            sB[(j * 4 + 2) * TPB + tid] = mul2_(mul2_(uu, v), thr2);
            sB[(j * 4 + 3) * TPB + tid] = mul2_(uu, u);
        }
    }
    __syncthreads();
    const u64* sC  = reinterpret_cast<const u64*>(sCf);
    const u64* myB = sB + tid;      // myB[(j*4+k)*TPB] = packed b_j[k]

    float dA, dB;

    // ---- dim 0: single differenced row, weight 1
    {
        float dc[16];
#pragma unroll
        for (int m = 0; m < 16; m++) dc[m] = sCf[m];
        dA = deriv16d(dc, __ldg(&x[s0 * 5 + 0]));
        dB = deriv16d(dc, __ldg(&x[s1 * 5 + 0]));
    }

    // ---- dim 1 (rowbase 1): 4 rows, fully unrolled
    {
        u64 aA[8], aB[8];
#pragma unroll
        for (int m = 0; m < 8; m++) { aA[m] = 0ULL; aB[m] = 0ULL; }
#pragma unroll
        for (int k0 = 0; k0 < 4; k0++)
            row_pw(sC, 1 + k0, myB[k0 * TPB], aA, aB);
        dA *= deriv16p(aA, __ldg(&x[s0 * 5 + 1]));
        dB *= deriv16p(aB, __ldg(&x[s1 * 5 + 1]));
    }

    // ---- dim 2 (rowbase 5): 16 rows, fully unrolled
    {
        u64 aA[8], aB[8];
#pragma unroll
        for (int m = 0; m < 8; m++) { aA[m] = 0ULL; aB[m] = 0ULL; }
#pragma unroll
        for (int k0 = 0; k0 < 4; k0++) {
            u64 w0 = myB[k0 * TPB];
#pragma unroll
            for (int k1 = 0; k1 < 4; k1++)
                row_pw(sC, 5 + k0 * 4 + k1, mul2_(w0, myB[(4 + k1) * TPB]), aA, aB);
        }
        dA *= deriv16p(aA, __ldg(&x[s0 * 5 + 2]));
        dB *= deriv16p(aB, __ldg(&x[s1 * 5 + 2]));
    }

    // ---- dim 3 (rowbase 21): outer k0 NOT unrolled -> 16-row window
    {
        u64 aA[8], aB[8];
#pragma unroll
        for (int m = 0; m < 8; m++) { aA[m] = 0ULL; aB[m] = 0ULL; }
        u64 b2c[4];
#pragma unroll
        for (int k = 0; k < 4; k++) b2c[k] = myB[(8 + k) * TPB];
#pragma unroll 1
        for (int k0 = 0; k0 < 4; k0++) {
            u64 w0 = myB[k0 * TPB];
            const int rb = 21 + k0 * 16;
#pragma unroll
            for (int k1 = 0; k1 < 4; k1++) {
                u64 w1 = mul2_(w0, myB[(4 + k1) * TPB]);
#pragma unroll
                for (int k2 = 0; k2 < 4; k2++)
                    row_pw(sC, rb + k1 * 4 + k2, mul2_(w1, b2c[k2]), aA, aB);
            }
        }
        dA *= deriv16p(aA, __ldg(&x[s0 * 5 + 3]));
        dB *= deriv16p(aB, __ldg(&x[s1 * 5 + 3]));
    }

    // ---- dim 4 (rowbase 85): outer k0,k1 NOT unrolled -> 16-row window
    {
        u64 aA[8], aB[8];
#pragma unroll
        for (int m = 0; m < 8; m++) { aA[m] = 0ULL; aB[m] = 0ULL; }
        u64 b2c[4], b3c[4];
#pragma unroll
        for (int k = 0; k < 4; k++) { b2c[k] = myB[(8 + k) * TPB]; b3c[k] = myB[(12 + k) * TPB]; }
#pragma unroll 1
        for (int k0 = 0; k0 < 4; k0++) {
            u64 w0 = myB[k0 * TPB];
#pragma unroll 1
            for (int k1 = 0; k1 < 4; k1++) {
                u64 w1 = mul2_(w0, myB[(4 + k1) * TPB]);
                const int rb = 85 + (k0 * 4 + k1) * 16;
#pragma unroll
                for (int k2 = 0; k2 < 4; k2++) {
                    u64 w2 = mul2_(w1, b2c[k2]);
#pragma unroll
                    for (int k3 = 0; k3 < 4; k3++)
                        row_pw(sC, rb + k2 * 4 + k3, mul2_(w2, b3c[k3]), aA, aB);
                }
            }
        }
        dA *= deriv16p(aA, __ldg(&x[s0 * 5 + 4]));
        dB *= deriv16p(aB, __ldg(&x[s1 * 5 + 4]));
    }

    out[s0] = dA;
    out[s1] = dB;
}

// ---------------------------------------------------------------------------
extern "C" void kernel_launch(void* const* d_in, const int* in_sizes, int n_in,
                              void* d_out, int out_size) {
    const float* x  = (const float*)d_in[0];
    const float* A0 = (const float*)d_in[1];
    const float* A1 = (const float*)d_in[2];
    const float* A2 = (const float*)d_in[3];
    const float* A3 = (const float*)d_in[4];
    const float* A4 = (const float*)d_in[5];
    float* out = (float*)d_out;

    bf_prep<<<1, 352>>>(A0, A1, A2, A3, A4);
    bf_main<<<NSAMP / (TPB * SPT), TPB>>>(x, out);   // 1024 blocks
}